// round 10
// baseline (speedup 1.0000x reference)
#include <cuda_runtime.h>
#include <math.h>
#include <stdint.h>

typedef unsigned long long ull;

#define TPB  512
#define NBLK 128
#define CSZ  4
#define NCLU 32
#define DB 512
#define DI 64
#define DH 256
#define DJ 64     /* j cols per CTA */
#define NB 16     /* batches per cluster */
#define DO 2
#define DT 200
#define HST 17    /* padded stride for h / hnew */
#define PSTR 9    /* ull stride per partial slot (bank-conflict pad) */
#define PSF 18    /* float stride per slot */

// ------------- static device scratch (weights duplicated {w,w}) -------------
__device__ ulonglong2 d_wdgxT[DI*DI/2];      // [k][i] dup, row = 32 ull2
__device__ ulonglong2 d_wdghT[DI*DH/2];      // [k][j] dup, row = 128 ull2
__device__ ulonglong2 d_wxzT[DI*DH/2], d_wmzT[DI*DH/2];
__device__ ulonglong2 d_wxrT[DI*DH/2], d_wmrT[DI*DH/2];
__device__ ulonglong2 d_wxhT[DI*DH/2], d_wmhT[DI*DH/2];
__device__ ulonglong2 d_whzT[DH*DH/2], d_whrT[DH*DH/2], d_whhT[DH*DH/2];
__device__ float d_psum[2][DH][NCLU];
__device__ float d_psq [2][DH][NCLU];
__device__ unsigned d_bar[DT];
__device__ unsigned g_count = 0;
__device__ volatile unsigned g_gen = 0;

// ---------------- shared layout (~143KB) ----------------
struct __align__(16) Smem {
    float in4[3*4*DI*NB];      // [c][u][i][b] staged 4 steps
    float ximp[2][DI*NB];      // double-buffered (parity), exchanged
    float xlast[16*NB];
    float xo4[16*NB*4];
    float hdec[DH*NB];         // full, exchanged
    float rh[DH*NB];           // full, exchanged
    float z[DJ*NB];
    float gbuf[DJ*NB];         // gamma_h(t+1)
    float h[DJ*HST];
    float hnew[DJ*HST];
    float a[DJ], c[DJ];
    float ypart[CSZ][32];
    ull   p[TPB*PSTR];         // padded partials
};

// ---------------- helpers ----------------
__device__ __forceinline__ void dfma(ull& d, ull a, ull b) {
    asm("fma.rn.f32x2 %0, %1, %2, %0;" : "+l"(d) : "l"(a), "l"(b));
}
__device__ __forceinline__ float sigf(float x) { return 1.f / (1.f + expf(-x)); }

__device__ __forceinline__ uint32_t s2u(const void* p) {
    uint32_t a;
    asm("{ .reg .u64 t; cvta.to.shared.u64 t, %1; cvt.u32.u64 %0, t; }" : "=r"(a) : "l"(p));
    return a;
}
__device__ __forceinline__ uint32_t mapa_(uint32_t a, uint32_t r) {
    uint32_t o; asm("mapa.shared::cluster.u32 %0, %1, %2;" : "=r"(o) : "r"(a), "r"(r));
    return o;
}
__device__ __forceinline__ void stc1(uint32_t a, float v) {
    asm volatile("st.shared::cluster.b32 [%0], %1;" :: "r"(a), "r"(__float_as_uint(v)) : "memory");
}
__device__ __forceinline__ void stc4(uint32_t a, float4 v) {
    asm volatile("st.shared::cluster.v4.b32 [%0], {%1,%2,%3,%4};" :: "r"(a),
        "r"(__float_as_uint(v.x)), "r"(__float_as_uint(v.y)),
        "r"(__float_as_uint(v.z)), "r"(__float_as_uint(v.w)) : "memory");
}
#define CLUSTER_SYNC() do { \
    asm volatile("barrier.cluster.arrive.aligned;" ::: "memory"); \
    asm volatile("barrier.cluster.wait.aligned;"   ::: "memory"); \
} while (0)

// dup weights [k][cols] ull2 row-stride W2; state v = [k][16b]; 8-deep prefetch.
// k-ranges MUST be multiples of 8.
template<int W2>
__device__ __forceinline__ void accGd(const ulonglong2* __restrict__ w, int wcol,
                                      const ulonglong2* __restrict__ v, int bq,
                                      int k0, int k1, ull* A) {
    for (int kb = k0; kb < k1; kb += 8) {
        ulonglong2 wb[8];
        #pragma unroll
        for (int q = 0; q < 8; q++)
            wb[q] = __ldg(&w[(size_t)(kb+q)*W2 + wcol]);
        #pragma unroll
        for (int q = 0; q < 8; q++) {
            int k = kb + q;
            ulonglong2 v0 = v[k*4 + bq*2], v1 = v[k*4 + bq*2 + 1];
            dfma(A[0], wb[q].x, v0.x); dfma(A[1], wb[q].x, v0.y);
            dfma(A[2], wb[q].x, v1.x); dfma(A[3], wb[q].x, v1.y);
            dfma(A[4], wb[q].y, v0.x); dfma(A[5], wb[q].y, v0.y);
            dfma(A[6], wb[q].y, v1.x); dfma(A[7], wb[q].y, v1.y);
        }
    }
}

__device__ __forceinline__ void stP(Smem* s, int slot, const ull* A) {
    ull* dst = &s->p[(size_t)slot*PSTR];
    #pragma unroll
    for (int q = 0; q < 8; q++) dst[q] = A[q];
}

// transpose + duplicate: dst_f2[k*J + j] = {src[j*K+k], src[j*K+k]}
__device__ __forceinline__ void tposeD(const float* __restrict__ src,
                                       ulonglong2* __restrict__ dstv,
                                       int J, int K, int g0, int gs) {
    float2* dst = (float2*)dstv;
    int n = J * K;
    for (int e = g0; e < n; e += gs) {
        int k = e / J, j = e - k * J;
        float v = src[j * K + k];
        dst[e] = make_float2(v, v);
    }
}

__device__ __forceinline__ void grid_barrier() {
    __syncthreads();
    if (threadIdx.x == 0) {
        __threadfence();
        unsigned gen = g_gen;
        if (atomicAdd(&g_count, 1u) == (unsigned)(gridDim.x - 1)) {
            g_count = 0u;
            __threadfence();
            g_gen = gen + 1u;
        } else {
            while (g_gen == gen) { __nanosleep(64); }
        }
        __threadfence();
    }
    __syncthreads();
}

__global__ void __cluster_dims__(CSZ,1,1) __launch_bounds__(TPB,1) grud_kernel(
    const float* __restrict__ in,     const float* __restrict__ x_mean,
    const float* __restrict__ w_dg_x, const float* __restrict__ b_dg_x,
    const float* __restrict__ w_dg_h, const float* __restrict__ b_dg_h,
    const float* __restrict__ w_xz,   const float* __restrict__ w_hz,
    const float* __restrict__ w_mz,   const float* __restrict__ b_z,
    const float* __restrict__ w_xr,   const float* __restrict__ w_hr,
    const float* __restrict__ w_mr,   const float* __restrict__ b_r,
    const float* __restrict__ w_xh,   const float* __restrict__ w_hh,
    const float* __restrict__ w_mh,   const float* __restrict__ b_h,
    const float* __restrict__ w_hy,   const float* __restrict__ b_hy,
    const float* __restrict__ bn_g,   const float* __restrict__ bn_b,
    float* __restrict__ out)
{
    extern __shared__ __align__(16) char raw[];
    Smem* s = (Smem*)raw;

    const int tid  = threadIdx.x;
    const int blk  = blockIdx.x;
    const int clu  = blk >> 2;
    const int rank = blk & 3;
    const int b0   = clu * NB;
    const int colbase = rank * DJ;

    float* __restrict__ out_y = out;
    float* __restrict__ out_h = out   + (size_t)DB * DT * DO;
    float* __restrict__ out_x = out_h + (size_t)DB * DT * DH;
    float* __restrict__ out_m = out_x + (size_t)DB * DI * DT;

    // -------- init: dup-transposes, counters, mask copy --------
    {
        int g0 = blk * TPB + tid, gs = NBLK * TPB;
        tposeD(w_dg_x, d_wdgxT, DI, DI, g0, gs);
        tposeD(w_dg_h, d_wdghT, DH, DI, g0, gs);
        tposeD(w_xz,   d_wxzT,  DH, DI, g0, gs);
        tposeD(w_mz,   d_wmzT,  DH, DI, g0, gs);
        tposeD(w_xr,   d_wxrT,  DH, DI, g0, gs);
        tposeD(w_mr,   d_wmrT,  DH, DI, g0, gs);
        tposeD(w_xh,   d_wxhT,  DH, DI, g0, gs);
        tposeD(w_mh,   d_wmhT,  DH, DI, g0, gs);
        tposeD(w_hz,   d_whzT,  DH, DH, g0, gs);
        tposeD(w_hr,   d_whrT,  DH, DH, g0, gs);
        tposeD(w_hh,   d_whhT,  DH, DH, g0, gs);
        if (blk == 0 && tid < DT) d_bar[tid] = 0u;
        for (int lb = 0; lb < 4; lb++) {
            int b = b0 + rank*4 + lb;
            const float4* src = (const float4*)(in + ((size_t)b*3 + 1) * DI * DT);
            float4* dst = (float4*)(out_m + (size_t)b * DI * DT);
            for (int e = tid; e < DI*DT/4; e += TPB) dst[e] = src[e];
        }
    }
    for (int e = tid; e < DJ*HST; e += TPB) s->h[e] = 0.f;
    for (int e = tid; e < DH*NB; e += TPB) s->hdec[e] = 0.f;
    if (tid < 16*NB) s->xlast[tid] = 0.f;

    grid_barrier();   // weights + counters visible

    const float* PF = (const float*)s->p;

    // -------- prologue: stage steps 0..3, Phase A for t=0 --------
    {
        for (int e = tid; e < 3*DI*NB; e += TPB) {
            int cc = e >> 10, r = e & 1023;
            int i = r >> 4, b = r & 15;
            float4 v = *(const float4*)&in[(((size_t)(b0+b)*3 + cc)*DI + i)*DT + 0];
            s->in4[((cc*4+0)*DI + i)*NB + b] = v.x;
            s->in4[((cc*4+1)*DI + i)*NB + b] = v.y;
            s->in4[((cc*4+2)*DI + i)*NB + b] = v.z;
            s->in4[((cc*4+3)*DI + i)*NB + b] = v.w;
        }
        __syncthreads();
        const ulonglong2* DD = (const ulonglong2*)&s->in4[(2*4+0)*DI*NB];
        if (tid < 256) {
            int jp = tid & 31, bq = (tid>>5)&1, ks = tid>>6;
            ull A[8] = {0,0,0,0,0,0,0,0};
            accGd<128>(d_wdghT, rank*32 + jp, DD, bq, ks*16, ks*16+16, A);
            stP(s, tid, A);
        } else if (tid < 384) {
            int idx = tid - 256;
            int ip = idx & 7, bq = (idx>>3)&1, ks = idx>>4;
            ull A[8] = {0,0,0,0,0,0,0,0};
            accGd<32>(d_wdgxT, rank*8 + ip, DD, bq, ks*8, ks*8+8, A);
            stP(s, tid, A);
        }
        __syncthreads();
        const float* Xc = &s->in4[(0*4+0)*DI*NB];
        const float* Mc = &s->in4[(1*4+0)*DI*NB];
        #pragma unroll
        for (int hf = 0; hf < 2; hf++) {
            int idx = hf*TPB + tid;
            int b = idx & 15, j = idx >> 4;
            int jp = j >> 1, lo = j & 1, bq = b >> 3, bo = b & 7;
            float f = 0.f;
            #pragma unroll
            for (int ks = 0; ks < 4; ks++) f += PF[(ks*64 + bq*32 + jp)*PSF + lo*8 + bo];
            s->gbuf[j*NB + b] = expf(-fmaxf(f + b_dg_h[colbase + j], 0.f));
        }
        if (tid < 256) {
            int il = tid >> 4, b = tid & 15;
            int ip = il >> 1, lo = il & 1, bq = b >> 3, bo = b & 7;
            int ig = rank*16 + il;
            float f = 0.f;
            #pragma unroll
            for (int ks = 0; ks < 8; ks++) f += PF[(256 + ks*16 + bq*8 + ip)*PSF + lo*8 + bo];
            float gg = expf(-fmaxf(f + b_dg_x[ig], 0.f));
            float mm = Mc[ig*NB + b], xx = Xc[ig*NB + b];
            float xl = (mm > 0.f) ? xx : s->xlast[il*NB + b];
            s->xlast[il*NB + b] = xl;
            float xv = mm*xx + (1.f-mm)*(gg*xl + (1.f-gg)*x_mean[ig]);
            s->ximp[0][ig*NB + b] = xv;
            uint32_t la = s2u(&s->ximp[0][ig*NB + b]);
            #pragma unroll
            for (int r = 0; r < CSZ; r++)
                if (r != rank) stc1(mapa_(la, (uint32_t)r), xv);
            s->xo4[(il*NB + b)*4 + 0] = xv;
        }
        CLUSTER_SYNC();
    }

    for (int t = 0; t < DT; t++) {
        const int u = t & 3;
        const ulonglong2* XI = (const ulonglong2*)s->ximp[t & 1];
        const ulonglong2* HD = (const ulonglong2*)s->hdec;
        const ulonglong2* RH = (const ulonglong2*)s->rh;
        const ulonglong2* MM = (const ulonglong2*)&s->in4[(1*4+u)*DI*NB];

        // ---- Phase B matmul: z (0..255) / r (256..511) ----
        {
            int g = tid >> 8, ks = (tid>>6)&3, bq = (tid>>5)&1, jp = tid & 31;
            const ulonglong2* wx = g ? d_wxrT : d_wxzT;
            const ulonglong2* wm = g ? d_wmrT : d_wmzT;
            const ulonglong2* wh = g ? d_whrT : d_whzT;
            int wc = rank*32 + jp;
            ull A[8] = {0,0,0,0,0,0,0,0};
            switch (ks) {
                case 0: accGd<128>(wx, wc, XI, bq, 0, 64, A);
                        accGd<128>(wm, wc, MM, bq, 0, 32, A); break;
                case 1: accGd<128>(wm, wc, MM, bq, 32, 64, A);
                        accGd<128>(wh, wc, HD, bq, 0, 64, A); break;
                case 2: accGd<128>(wh, wc, HD, bq, 64, 160, A); break;
                default: accGd<128>(wh, wc, HD, bq, 160, 256, A); break;
            }
            stP(s, tid, A);
        }
        __syncthreads();

        // ---- Phase B combine: z local; rh = r*hdec + exchange (float4) ----
        if (tid < 256) {
            int bq4 = tid >> 6, j = tid & 63;
            int jp = j >> 1, lo = j & 1, jg = colbase + j;
            float bzv = b_z[jg], brv = b_r[jg];
            float4 rv; float* rp = (float*)&rv;
            #pragma unroll
            for (int u2 = 0; u2 < 4; u2++) {
                int b = bq4*4 + u2, bq = b >> 3, bo = b & 7;
                float fz = 0.f, fr = 0.f;
                #pragma unroll
                for (int ks = 0; ks < 4; ks++) {
                    int base = (ks*64 + bq*32 + jp)*PSF + lo*8 + bo;
                    fz += PF[base];
                    fr += PF[256*PSF + base];
                }
                s->z[j*NB + b] = sigf(fz + bzv);
                rp[u2] = sigf(fr + brv) * s->hdec[jg*NB + b];
            }
            *(float4*)&s->rh[jg*NB + bq4*4] = rv;
            uint32_t la = s2u(&s->rh[jg*NB + bq4*4]);
            #pragma unroll
            for (int r = 0; r < CSZ; r++)
                if (r != rank) stc4(mapa_(la, (uint32_t)r), rv);
        }
        CLUSTER_SYNC();   // rh full everywhere

        // ---- Phase C matmul: h_tilde preact, 8 k-splits ----
        {
            int ks = tid >> 6, bq = (tid>>5)&1, jp = tid & 31;
            int wc = rank*32 + jp;
            ull A[8] = {0,0,0,0,0,0,0,0};
            switch (ks) {
                case 0: accGd<128>(d_wxhT, wc, XI, bq, 0, 48, A); break;
                case 1: accGd<128>(d_wxhT, wc, XI, bq, 48, 64, A);
                        accGd<128>(d_wmhT, wc, MM, bq, 0, 32, A); break;
                case 2: accGd<128>(d_wmhT, wc, MM, bq, 32, 64, A);
                        accGd<128>(d_whhT, wc, RH, bq, 0, 16, A); break;
                case 3: accGd<128>(d_whhT, wc, RH, bq, 16, 64, A); break;
                case 4: accGd<128>(d_whhT, wc, RH, bq, 64, 112, A); break;
                case 5: accGd<128>(d_whhT, wc, RH, bq, 112, 160, A); break;
                case 6: accGd<128>(d_whhT, wc, RH, bq, 160, 208, A); break;
                default: accGd<128>(d_whhT, wc, RH, bq, 208, 256, A); break;
            }
            stP(s, tid, A);
        }
        __syncthreads();

        // ---- Phase C combine (tid<256) + restage in4 (all threads) ----
        if (tid < 256) {
            int j = tid >> 2, bq4 = tid & 3;
            int jp = j >> 1, lo = j & 1, jg = colbase + j;
            float bh = b_h[jg];
            float ps = 0.f, pq = 0.f;
            #pragma unroll
            for (int u2 = 0; u2 < 4; u2++) {
                int b = bq4*4 + u2, bq = b >> 3, bo = b & 7;
                float f = bh;
                #pragma unroll
                for (int ks = 0; ks < 8; ks++)
                    f += PF[(ks*64 + bq*32 + jp)*PSF + lo*8 + bo];
                float ht = tanhf(f);
                float zz = s->z[j*NB + b], hd = s->hdec[jg*NB + b];
                float h1 = (1.f - zz)*hd + zz*ht;
                s->hnew[j*HST + b] = h1;
                ps += h1; pq += h1*h1;
            }
            ps += __shfl_xor_sync(0xffffffffu, ps, 1);
            ps += __shfl_xor_sync(0xffffffffu, ps, 2);
            pq += __shfl_xor_sync(0xffffffffu, pq, 1);
            pq += __shfl_xor_sync(0xffffffffu, pq, 2);
            if (bq4 == 0) {
                int buf = t & 1;
                d_psum[buf][jg][clu] = ps;
                d_psq [buf][jg][clu] = pq;
            }
        }
        if ((t+1) < DT && (((t+1) & 3) == 0)) {
            for (int e = tid; e < 3*DI*NB; e += TPB) {
                int cc = e >> 10, r = e & 1023;
                int i = r >> 4, b = r & 15;
                float4 v = *(const float4*)&in[(((size_t)(b0+b)*3 + cc)*DI + i)*DT + (t+1)];
                s->in4[((cc*4+0)*DI + i)*NB + b] = v.x;
                s->in4[((cc*4+1)*DI + i)*NB + b] = v.y;
                s->in4[((cc*4+2)*DI + i)*NB + b] = v.z;
                s->in4[((cc*4+3)*DI + i)*NB + b] = v.w;
            }
        }
        __syncthreads();

        // ---- arrive at grid barrier, then Phase A(t+1) in its shadow ----
        if (tid == 0) { __threadfence(); atomicAdd(&d_bar[t], 1u); }

        if ((t+1) < DT) {
            const int u1 = (t+1) & 3;
            const ulonglong2* DD = (const ulonglong2*)&s->in4[(2*4+u1)*DI*NB];
            if (tid < 256) {
                int jp = tid & 31, bq = (tid>>5)&1, ks = tid>>6;
                ull A[8] = {0,0,0,0,0,0,0,0};
                accGd<128>(d_wdghT, rank*32 + jp, DD, bq, ks*16, ks*16+16, A);
                stP(s, tid, A);
            } else if (tid < 384) {
                int idx = tid - 256;
                int ip = idx & 7, bq = (idx>>3)&1, ks = idx>>4;
                ull A[8] = {0,0,0,0,0,0,0,0};
                accGd<32>(d_wdgxT, rank*8 + ip, DD, bq, ks*8, ks*8+8, A);
                stP(s, tid, A);
            }
        }
        __syncthreads();
        if ((t+1) < DT) {
            const int u1 = (t+1) & 3;
            const int par = (t+1) & 1;
            const float* Xc = &s->in4[(0*4+u1)*DI*NB];
            const float* Mc = &s->in4[(1*4+u1)*DI*NB];
            #pragma unroll
            for (int hf = 0; hf < 2; hf++) {
                int idx = hf*TPB + tid;
                int b = idx & 15, j = idx >> 4;
                int jp = j >> 1, lo = j & 1, bq = b >> 3, bo = b & 7;
                float f = 0.f;
                #pragma unroll
                for (int ks = 0; ks < 4; ks++)
                    f += PF[(ks*64 + bq*32 + jp)*PSF + lo*8 + bo];
                s->gbuf[j*NB + b] = expf(-fmaxf(f + b_dg_h[colbase + j], 0.f));
            }
            if (tid < 256) {
                int il = tid >> 4, b = tid & 15;
                int ip = il >> 1, lo = il & 1, bq = b >> 3, bo = b & 7;
                int ig = rank*16 + il;
                float f = 0.f;
                #pragma unroll
                for (int ks = 0; ks < 8; ks++)
                    f += PF[(256 + ks*16 + bq*8 + ip)*PSF + lo*8 + bo];
                float gg = expf(-fmaxf(f + b_dg_x[ig], 0.f));
                float mm = Mc[ig*NB + b], xx = Xc[ig*NB + b];
                float xl = (mm > 0.f) ? xx : s->xlast[il*NB + b];
                s->xlast[il*NB + b] = xl;
                float xv = mm*xx + (1.f-mm)*(gg*xl + (1.f-gg)*x_mean[ig]);
                s->ximp[par][ig*NB + b] = xv;
                uint32_t la = s2u(&s->ximp[par][ig*NB + b]);
                #pragma unroll
                for (int r = 0; r < CSZ; r++)
                    if (r != rank) stc1(mapa_(la, (uint32_t)r), xv);
                s->xo4[(il*NB + b)*4 + u1] = xv;
                if (u1 == 3)
                    *(float4*)&out_x[((size_t)(b0+b)*DI + ig)*DT + (t+1) - 3] =
                        *(const float4*)&s->xo4[(il*NB + b)*4];
            }
        }
        __syncthreads();

        // ---- wait for all CTAs ----
        if (tid == 0) {
            while (*(volatile unsigned*)&d_bar[t] < (unsigned)NBLK) { __nanosleep(32); }
            __threadfence();
        }
        __syncthreads();

        // ---- Phase D: BN stats ----
        if (tid < DJ) {
            int jg = colbase + tid, buf = t & 1;
            const float4* ps = (const float4*)d_psum[buf][jg];
            const float4* pq = (const float4*)d_psq [buf][jg];
            float s1 = 0.f, s2 = 0.f;
            #pragma unroll
            for (int pp = 0; pp < NCLU/4; pp++) {
                float4 a4 = __ldcg(ps + pp);
                float4 c4 = __ldcg(pq + pp);
                s1 += (a4.x + a4.y) + (a4.z + a4.w);
                s2 += (c4.x + c4.y) + (c4.z + c4.w);
            }
            float mu  = s1 * (1.f/(float)DB);
            float var = fmaf(s2, 1.f/(float)DB, -mu*mu);
            float rs  = rsqrtf(var + 1e-5f);
            float aa  = rs * bn_g[jg];
            s->a[tid] = aa;
            s->c[tid] = fmaf(-mu, aa, bn_b[jg]);
        }
        __syncthreads();

        // ---- Phase E: normalize, carry h, coalesced out_h, hdec(t+1) ----
        if (tid < 256) {
            int bq4 = tid >> 6, j = tid & 63, jg = colbase + j;
            float aa = s->a[j], cc = s->c[j];
            float4 hd4; float* hp = (float*)&hd4;
            #pragma unroll
            for (int u2 = 0; u2 < 4; u2++) {
                int b = bq4*4 + u2;
                float hb = fmaf(s->hnew[j*HST + b], aa, cc);
                s->h[j*HST + b] = hb;
                out_h[((size_t)(b0+b)*DT + t)*DH + jg] = hb;
                hp[u2] = s->gbuf[j*NB + b] * hb;
            }
            *(float4*)&s->hdec[jg*NB + bq4*4] = hd4;
            uint32_t la = s2u(&s->hdec[jg*NB + bq4*4]);
            #pragma unroll
            for (int r = 0; r < CSZ; r++)
                if (r != rank) stc4(mapa_(la, (uint32_t)r), hd4);
        }
        __syncthreads();

        // ---- Phase F: distributed y-head (16 warps x 2 tasks) ----
        {
            int w = tid >> 5, lane = tid & 31;
            #pragma unroll
            for (int it = 0; it < 2; it++) {
                int task = w*2 + it;
                int b = task >> 1, o = task & 1;
                float acc = s->h[lane*HST + b]      * __ldg(&w_hy[o*DH + colbase + lane])
                          + s->h[(lane+32)*HST + b] * __ldg(&w_hy[o*DH + colbase + lane + 32]);
                #pragma unroll
                for (int off = 16; off; off >>= 1)
                    acc += __shfl_xor_sync(0xffffffffu, acc, off);
                if (lane == 0) {
                    if (rank == 0) s->ypart[0][task] = acc;
                    else stc1(mapa_(s2u(&s->ypart[rank][task]), 0u), acc);
                }
            }
        }
        CLUSTER_SYNC();   // ypart + hdec + ximp exchanges complete
        if (rank == 0 && tid < 32) {
            int b = tid >> 1, o = tid & 1;
            float v = s->ypart[0][tid] + s->ypart[1][tid]
                    + s->ypart[2][tid] + s->ypart[3][tid] + b_hy[o];
            out_y[((size_t)(b0+b)*DT + t)*DO + o] = 1.f / (1.f + expf(-v));
        }
        __syncthreads();
    }
}

extern "C" void kernel_launch(void* const* d_in, const int* in_sizes, int n_in,
                              void* d_out, int out_size) {
    cudaFuncSetAttribute(grud_kernel, cudaFuncAttributeMaxDynamicSharedMemorySize,
                         (int)sizeof(Smem));
    grud_kernel<<<NBLK, TPB, sizeof(Smem)>>>(
        (const float*)d_in[0],  (const float*)d_in[1],
        (const float*)d_in[2],  (const float*)d_in[3],
        (const float*)d_in[4],  (const float*)d_in[5],
        (const float*)d_in[6],  (const float*)d_in[7],
        (const float*)d_in[8],  (const float*)d_in[9],
        (const float*)d_in[10], (const float*)d_in[11],
        (const float*)d_in[12], (const float*)d_in[13],
        (const float*)d_in[14], (const float*)d_in[15],
        (const float*)d_in[16], (const float*)d_in[17],
        (const float*)d_in[18], (const float*)d_in[19],
        (const float*)d_in[20], (const float*)d_in[21],
        (float*)d_out);
}

// round 11
// speedup vs baseline: 1.0477x; 1.0477x over previous
#include <cuda_runtime.h>
#include <math.h>
#include <stdint.h>

typedef unsigned long long ull;

#define TPB  512
#define NBLK 128
#define CSZ  4
#define NCLU 32
#define DB 512
#define DI 64
#define DH 256
#define DJ 64     /* j cols per CTA */
#define NB 16     /* batches per cluster */
#define DO 2
#define DT 200
#define HST 17    /* padded stride for h / hnew */
#define PSTR 9    /* ull stride per partial slot (bank-conflict pad) */
#define PSF 18    /* float stride per slot */

// ---------------- static device scratch ----------------
__device__ float d_wdgxT[DI*DI];
__device__ float d_wdghT[DI*DH];
__device__ float d_wxzT[DI*DH], d_wmzT[DI*DH];
__device__ float d_wxrT[DI*DH], d_wmrT[DI*DH];
__device__ float d_wxhT[DI*DH], d_wmhT[DI*DH];
__device__ float d_whzT[DH*DH], d_whrT[DH*DH], d_whhT[DH*DH];
__device__ float d_psum[2][DH][NCLU];
__device__ float d_psq [2][DH][NCLU];
__device__ unsigned d_bar[DT];
__device__ unsigned g_count = 0;
__device__ volatile unsigned g_gen = 0;

// ---------------- shared layout (~155KB) ----------------
struct __align__(16) Smem {
    float in4[3*4*DI*NB];      // [c][u][i][b] staged 4 steps
    float ximp[2][DI*NB];      // double-buffered (parity), exchanged
    float xlast[16*NB];
    float xo4[16*NB*4];
    float hdec[DH*NB];         // full, exchanged
    float rh[DH*NB];           // full, exchanged
    float z[DJ*NB];
    float gbuf[DJ*NB];         // gamma_h(t+1)
    float zxm[DJ*NB];          // x/m contribution to z preact (next step)
    float rxm[DJ*NB];
    float hxm[DJ*NB];
    float h[DJ*HST];
    float hnew[DJ*HST];
    float a[DJ], c[DJ];
    float ypart[CSZ][32];
    ull   p[TPB*PSTR];         // padded partials
};

// ---------------- helpers ----------------
__device__ __forceinline__ ull pk(float w) {
    ull r; unsigned u = __float_as_uint(w);
    asm("mov.b64 %0, {%1, %1};" : "=l"(r) : "r"(u));
    return r;
}
__device__ __forceinline__ void dfma(ull& d, ull a, ull b) {
    asm("fma.rn.f32x2 %0, %1, %2, %0;" : "+l"(d) : "l"(a), "l"(b));
}
__device__ __forceinline__ float sigf(float x) { return 1.f / (1.f + expf(-x)); }

__device__ __forceinline__ uint32_t s2u(const void* p) {
    uint32_t a;
    asm("{ .reg .u64 t; cvta.to.shared.u64 t, %1; cvt.u32.u64 %0, t; }" : "=r"(a) : "l"(p));
    return a;
}
__device__ __forceinline__ uint32_t mapa_(uint32_t a, uint32_t r) {
    uint32_t o; asm("mapa.shared::cluster.u32 %0, %1, %2;" : "=r"(o) : "r"(a), "r"(r));
    return o;
}
__device__ __forceinline__ void stc1(uint32_t a, float v) {
    asm volatile("st.shared::cluster.b32 [%0], %1;" :: "r"(a), "r"(__float_as_uint(v)) : "memory");
}
__device__ __forceinline__ void stc4(uint32_t a, float4 v) {
    asm volatile("st.shared::cluster.v4.b32 [%0], {%1,%2,%3,%4};" :: "r"(a),
        "r"(__float_as_uint(v.x)), "r"(__float_as_uint(v.y)),
        "r"(__float_as_uint(v.z)), "r"(__float_as_uint(v.w)) : "memory");
}
#define CLUSTER_SYNC() do { \
    asm volatile("barrier.cluster.arrive.aligned;" ::: "memory"); \
    asm volatile("barrier.cluster.wait.aligned;"   ::: "memory"); \
} while (0)

// streamed weights [k][cols] float2 stride WS; state v = [k][16b]
template<int WS>
__device__ __forceinline__ void accG(const float2* __restrict__ w, int wcol,
                                     const ulonglong2* __restrict__ v, int bq,
                                     int k0, int k1, ull* A) {
    #pragma unroll 8
    for (int k = k0; k < k1; k++) {
        float2 ww = __ldg(&w[(size_t)k*WS + wcol]);
        ulonglong2 v0 = v[k*4 + bq*2], v1 = v[k*4 + bq*2 + 1];
        ull w0 = pk(ww.x), w1 = pk(ww.y);
        dfma(A[0], w0, v0.x); dfma(A[1], w0, v0.y);
        dfma(A[2], w0, v1.x); dfma(A[3], w0, v1.y);
        dfma(A[4], w1, v0.x); dfma(A[5], w1, v0.y);
        dfma(A[6], w1, v1.x); dfma(A[7], w1, v1.y);
    }
}

__device__ __forceinline__ void stP(Smem* s, int slot, const ull* A) {
    ull* dst = &s->p[(size_t)slot*PSTR];
    #pragma unroll
    for (int q = 0; q < 8; q++) dst[q] = A[q];
}

__device__ __forceinline__ void tpose(const float* __restrict__ src,
                                      float* __restrict__ dst,
                                      int J, int K, int g0, int gs) {
    int n = J * K;
    for (int e = g0; e < n; e += gs) {
        int k = e / J, j = e - k * J;
        dst[e] = src[j * K + k];
    }
}

__device__ __forceinline__ void grid_barrier() {
    __syncthreads();
    if (threadIdx.x == 0) {
        __threadfence();
        unsigned gen = g_gen;
        if (atomicAdd(&g_count, 1u) == (unsigned)(gridDim.x - 1)) {
            g_count = 0u;
            __threadfence();
            g_gen = gen + 1u;
        } else {
            while (g_gen == gen) { __nanosleep(64); }
        }
        __threadfence();
    }
    __syncthreads();
}

// shadowed x/m matmul for gates z,r,h (gate-pure k-slices)
__device__ __forceinline__ void xm_matmul(Smem* s, int tid, int rank,
                                          const ulonglong2* XI,
                                          const ulonglong2* MM) {
    int gs = tid >> 6, bq = (tid>>5)&1, jp = tid & 31;
    int wc = rank*32 + jp;
    const float2* wxz2 = (const float2*)d_wxzT;
    const float2* wmz2 = (const float2*)d_wmzT;
    const float2* wxr2 = (const float2*)d_wxrT;
    const float2* wmr2 = (const float2*)d_wmrT;
    const float2* wxh2 = (const float2*)d_wxhT;
    const float2* wmh2 = (const float2*)d_wmhT;
    ull A[8] = {0,0,0,0,0,0,0,0};
    switch (gs) {
        case 0: accG<128>(wxz2, wc, XI, bq, 0, 43, A); break;
        case 1: accG<128>(wxz2, wc, XI, bq, 43, 64, A);
                accG<128>(wmz2, wc, MM, bq, 0, 22, A); break;
        case 2: accG<128>(wmz2, wc, MM, bq, 22, 64, A); break;
        case 3: accG<128>(wxr2, wc, XI, bq, 0, 43, A); break;
        case 4: accG<128>(wxr2, wc, XI, bq, 43, 64, A);
                accG<128>(wmr2, wc, MM, bq, 0, 22, A); break;
        case 5: accG<128>(wmr2, wc, MM, bq, 22, 64, A); break;
        case 6: accG<128>(wxh2, wc, XI, bq, 0, 64, A); break;
        default: accG<128>(wmh2, wc, MM, bq, 0, 64, A); break;
    }
    stP(s, tid, A);
}

// combine xm partials into compact per-(j,b) arrays
__device__ __forceinline__ void xm_combine(Smem* s, int tid, const float* PF) {
    #pragma unroll
    for (int hf = 0; hf < 2; hf++) {
        int idx = hf*TPB + tid;
        int b = idx & 15, j = idx >> 4;
        int jp = j >> 1, lo = j & 1, bq = b >> 3, bo = b & 7;
        int off = (bq*32 + jp)*PSF + lo*8 + bo;
        float zv = PF[off] + PF[64*PSF + off] + PF[128*PSF + off];
        float rv = PF[192*PSF + off] + PF[256*PSF + off] + PF[320*PSF + off];
        float hv = PF[384*PSF + off] + PF[448*PSF + off];
        s->zxm[j*NB + b] = zv;
        s->rxm[j*NB + b] = rv;
        s->hxm[j*NB + b] = hv;
    }
}

__global__ void __cluster_dims__(CSZ,1,1) __launch_bounds__(TPB,1) grud_kernel(
    const float* __restrict__ in,     const float* __restrict__ x_mean,
    const float* __restrict__ w_dg_x, const float* __restrict__ b_dg_x,
    const float* __restrict__ w_dg_h, const float* __restrict__ b_dg_h,
    const float* __restrict__ w_xz,   const float* __restrict__ w_hz,
    const float* __restrict__ w_mz,   const float* __restrict__ b_z,
    const float* __restrict__ w_xr,   const float* __restrict__ w_hr,
    const float* __restrict__ w_mr,   const float* __restrict__ b_r,
    const float* __restrict__ w_xh,   const float* __restrict__ w_hh,
    const float* __restrict__ w_mh,   const float* __restrict__ b_h,
    const float* __restrict__ w_hy,   const float* __restrict__ b_hy,
    const float* __restrict__ bn_g,   const float* __restrict__ bn_b,
    float* __restrict__ out)
{
    extern __shared__ __align__(16) char raw[];
    Smem* s = (Smem*)raw;

    const int tid  = threadIdx.x;
    const int blk  = blockIdx.x;
    const int clu  = blk >> 2;
    const int rank = blk & 3;
    const int b0   = clu * NB;
    const int colbase = rank * DJ;

    float* __restrict__ out_y = out;
    float* __restrict__ out_h = out   + (size_t)DB * DT * DO;
    float* __restrict__ out_x = out_h + (size_t)DB * DT * DH;
    float* __restrict__ out_m = out_x + (size_t)DB * DI * DT;

    // -------- init: transposes, counters, mask copy --------
    {
        int g0 = blk * TPB + tid, gs = NBLK * TPB;
        tpose(w_dg_x, d_wdgxT, DI, DI, g0, gs);
        tpose(w_dg_h, d_wdghT, DH, DI, g0, gs);
        tpose(w_xz,   d_wxzT,  DH, DI, g0, gs);
        tpose(w_mz,   d_wmzT,  DH, DI, g0, gs);
        tpose(w_xr,   d_wxrT,  DH, DI, g0, gs);
        tpose(w_mr,   d_wmrT,  DH, DI, g0, gs);
        tpose(w_xh,   d_wxhT,  DH, DI, g0, gs);
        tpose(w_mh,   d_wmhT,  DH, DI, g0, gs);
        tpose(w_hz,   d_whzT,  DH, DH, g0, gs);
        tpose(w_hr,   d_whrT,  DH, DH, g0, gs);
        tpose(w_hh,   d_whhT,  DH, DH, g0, gs);
        if (blk == 0 && tid < DT) d_bar[tid] = 0u;
        for (int lb = 0; lb < 4; lb++) {
            int b = b0 + rank*4 + lb;
            const float4* src = (const float4*)(in + ((size_t)b*3 + 1) * DI * DT);
            float4* dst = (float4*)(out_m + (size_t)b * DI * DT);
            for (int e = tid; e < DI*DT/4; e += TPB) dst[e] = src[e];
        }
    }
    for (int e = tid; e < DJ*HST; e += TPB) s->h[e] = 0.f;
    for (int e = tid; e < DH*NB; e += TPB) s->hdec[e] = 0.f;
    if (tid < 16*NB) s->xlast[tid] = 0.f;

    grid_barrier();   // weights + counters visible

    const float* PF = (const float*)s->p;

    // -------- prologue: stage steps 0..3, Phase A(0), xm(0) --------
    {
        for (int e = tid; e < 3*DI*NB; e += TPB) {
            int cc = e >> 10, r = e & 1023;
            int i = r >> 4, b = r & 15;
            float4 v = *(const float4*)&in[(((size_t)(b0+b)*3 + cc)*DI + i)*DT + 0];
            s->in4[((cc*4+0)*DI + i)*NB + b] = v.x;
            s->in4[((cc*4+1)*DI + i)*NB + b] = v.y;
            s->in4[((cc*4+2)*DI + i)*NB + b] = v.z;
            s->in4[((cc*4+3)*DI + i)*NB + b] = v.w;
        }
        __syncthreads();
        const ulonglong2* DD = (const ulonglong2*)&s->in4[(2*4+0)*DI*NB];
        if (tid < 256) {
            int jp = tid & 31, bq = (tid>>5)&1, ks = tid>>6;
            ull A[8] = {0,0,0,0,0,0,0,0};
            accG<128>((const float2*)d_wdghT, rank*32 + jp, DD, bq, ks*16, ks*16+16, A);
            stP(s, tid, A);
        } else if (tid < 384) {
            int idx = tid - 256;
            int ip = idx & 7, bq = (idx>>3)&1, ks = idx>>4;
            ull A[8] = {0,0,0,0,0,0,0,0};
            accG<32>((const float2*)d_wdgxT, rank*8 + ip, DD, bq, ks*8, ks*8+8, A);
            stP(s, tid, A);
        }
        __syncthreads();
        const float* Xc = &s->in4[(0*4+0)*DI*NB];
        const float* Mc = &s->in4[(1*4+0)*DI*NB];
        #pragma unroll
        for (int hf = 0; hf < 2; hf++) {
            int idx = hf*TPB + tid;
            int b = idx & 15, j = idx >> 4;
            int jp = j >> 1, lo = j & 1, bq = b >> 3, bo = b & 7;
            float f = 0.f;
            #pragma unroll
            for (int ks = 0; ks < 4; ks++) f += PF[(ks*64 + bq*32 + jp)*PSF + lo*8 + bo];
            s->gbuf[j*NB + b] = expf(-fmaxf(f + b_dg_h[colbase + j], 0.f));
        }
        if (tid < 256) {
            int il = tid >> 4, b = tid & 15;
            int ip = il >> 1, lo = il & 1, bq = b >> 3, bo = b & 7;
            int ig = rank*16 + il;
            float f = 0.f;
            #pragma unroll
            for (int ks = 0; ks < 8; ks++) f += PF[(256 + ks*16 + bq*8 + ip)*PSF + lo*8 + bo];
            float gg = expf(-fmaxf(f + b_dg_x[ig], 0.f));
            float mm = Mc[ig*NB + b], xx = Xc[ig*NB + b];
            float xl = (mm > 0.f) ? xx : s->xlast[il*NB + b];
            s->xlast[il*NB + b] = xl;
            float xv = mm*xx + (1.f-mm)*(gg*xl + (1.f-gg)*x_mean[ig]);
            s->ximp[0][ig*NB + b] = xv;
            uint32_t la = s2u(&s->ximp[0][ig*NB + b]);
            #pragma unroll
            for (int r = 0; r < CSZ; r++)
                if (r != rank) stc1(mapa_(la, (uint32_t)r), xv);
            s->xo4[(il*NB + b)*4 + 0] = xv;
        }
        CLUSTER_SYNC();   // ximp(0) full everywhere
        xm_matmul(s, tid, rank, (const ulonglong2*)s->ximp[0],
                  (const ulonglong2*)&s->in4[(1*4+0)*DI*NB]);
        __syncthreads();
        xm_combine(s, tid, PF);
        __syncthreads();
    }

    for (int t = 0; t < DT; t++) {
        const ulonglong2* HD = (const ulonglong2*)s->hdec;
        const ulonglong2* RH = (const ulonglong2*)s->rh;

        // ---- Phase B_h matmul: whz/whr · hdec only ----
        {
            int g = tid >> 8, ks = (tid>>6)&3, bq = (tid>>5)&1, jp = tid & 31;
            const float2* wh = (const float2*)(g ? d_whrT : d_whzT);
            int wc = rank*32 + jp;
            ull A[8] = {0,0,0,0,0,0,0,0};
            accG<128>(wh, wc, HD, bq, ks*64, ks*64+64, A);
            stP(s, tid, A);
        }
        __syncthreads();

        // ---- Phase B combine: z = sig(zxm + hpart); rh exchange ----
        if (tid < 256) {
            int bq4 = tid >> 6, j = tid & 63;
            int jp = j >> 1, lo = j & 1, jg = colbase + j;
            float bzv = b_z[jg], brv = b_r[jg];
            float4 rv; float* rp = (float*)&rv;
            #pragma unroll
            for (int u2 = 0; u2 < 4; u2++) {
                int b = bq4*4 + u2, bq = b >> 3, bo = b & 7;
                float fz = s->zxm[j*NB + b], fr = s->rxm[j*NB + b];
                #pragma unroll
                for (int ks = 0; ks < 4; ks++) {
                    int base = (ks*64 + bq*32 + jp)*PSF + lo*8 + bo;
                    fz += PF[base];
                    fr += PF[256*PSF + base];
                }
                s->z[j*NB + b] = sigf(fz + bzv);
                rp[u2] = sigf(fr + brv) * s->hdec[jg*NB + b];
            }
            *(float4*)&s->rh[jg*NB + bq4*4] = rv;
            uint32_t la = s2u(&s->rh[jg*NB + bq4*4]);
            #pragma unroll
            for (int r = 0; r < CSZ; r++)
                if (r != rank) stc4(mapa_(la, (uint32_t)r), rv);
        }
        CLUSTER_SYNC();   // rh full everywhere

        // ---- Phase C_h matmul: whh · rh only, 8 k-splits of 32 ----
        {
            int ks = tid >> 6, bq = (tid>>5)&1, jp = tid & 31;
            int wc = rank*32 + jp;
            ull A[8] = {0,0,0,0,0,0,0,0};
            accG<128>((const float2*)d_whhT, wc, RH, bq, ks*32, ks*32+32, A);
            stP(s, tid, A);
        }
        __syncthreads();

        // ---- Phase C combine (tid<256) + restage in4 (all threads) ----
        if (tid < 256) {
            int j = tid >> 2, bq4 = tid & 3;
            int jp = j >> 1, lo = j & 1, jg = colbase + j;
            float bh = b_h[jg];
            float ps = 0.f, pq = 0.f;
            #pragma unroll
            for (int u2 = 0; u2 < 4; u2++) {
                int b = bq4*4 + u2, bq = b >> 3, bo = b & 7;
                float f = bh + s->hxm[j*NB + b];
                #pragma unroll
                for (int ks = 0; ks < 8; ks++)
                    f += PF[(ks*64 + bq*32 + jp)*PSF + lo*8 + bo];
                float ht = tanhf(f);
                float zz = s->z[j*NB + b], hd = s->hdec[jg*NB + b];
                float h1 = (1.f - zz)*hd + zz*ht;
                s->hnew[j*HST + b] = h1;
                ps += h1; pq += h1*h1;
            }
            ps += __shfl_xor_sync(0xffffffffu, ps, 1);
            ps += __shfl_xor_sync(0xffffffffu, ps, 2);
            pq += __shfl_xor_sync(0xffffffffu, pq, 1);
            pq += __shfl_xor_sync(0xffffffffu, pq, 2);
            if (bq4 == 0) {
                int buf = t & 1;
                d_psum[buf][jg][clu] = ps;
                d_psq [buf][jg][clu] = pq;
            }
        }
        if ((t+1) < DT && (((t+1) & 3) == 0)) {
            for (int e = tid; e < 3*DI*NB; e += TPB) {
                int cc = e >> 10, r = e & 1023;
                int i = r >> 4, b = r & 15;
                float4 v = *(const float4*)&in[(((size_t)(b0+b)*3 + cc)*DI + i)*DT + (t+1)];
                s->in4[((cc*4+0)*DI + i)*NB + b] = v.x;
                s->in4[((cc*4+1)*DI + i)*NB + b] = v.y;
                s->in4[((cc*4+2)*DI + i)*NB + b] = v.z;
                s->in4[((cc*4+3)*DI + i)*NB + b] = v.w;
            }
        }
        __syncthreads();

        // ---- arrive at grid barrier, then t+1 pre-work in its shadow ----
        if (tid == 0) { __threadfence(); atomicAdd(&d_bar[t], 1u); }

        if ((t+1) < DT) {
            const int u1 = (t+1) & 3;
            const ulonglong2* DD = (const ulonglong2*)&s->in4[(2*4+u1)*DI*NB];
            if (tid < 256) {
                int jp = tid & 31, bq = (tid>>5)&1, ks = tid>>6;
                ull A[8] = {0,0,0,0,0,0,0,0};
                accG<128>((const float2*)d_wdghT, rank*32 + jp, DD, bq, ks*16, ks*16+16, A);
                stP(s, tid, A);
            } else if (tid < 384) {
                int idx = tid - 256;
                int ip = idx & 7, bq = (idx>>3)&1, ks = idx>>4;
                ull A[8] = {0,0,0,0,0,0,0,0};
                accG<32>((const float2*)d_wdgxT, rank*8 + ip, DD, bq, ks*8, ks*8+8, A);
                stP(s, tid, A);
            }
            __syncthreads();
            const int par = (t+1) & 1;
            const float* Xc = &s->in4[(0*4+u1)*DI*NB];
            const float* Mc = &s->in4[(1*4+u1)*DI*NB];
            #pragma unroll
            for (int hf = 0; hf < 2; hf++) {
                int idx = hf*TPB + tid;
                int b = idx & 15, j = idx >> 4;
                int jp = j >> 1, lo = j & 1, bq = b >> 3, bo = b & 7;
                float f = 0.f;
                #pragma unroll
                for (int ks = 0; ks < 4; ks++)
                    f += PF[(ks*64 + bq*32 + jp)*PSF + lo*8 + bo];
                s->gbuf[j*NB + b] = expf(-fmaxf(f + b_dg_h[colbase + j], 0.f));
            }
            if (tid < 256) {
                int il = tid >> 4, b = tid & 15;
                int ip = il >> 1, lo = il & 1, bq = b >> 3, bo = b & 7;
                int ig = rank*16 + il;
                float f = 0.f;
                #pragma unroll
                for (int ks = 0; ks < 8; ks++)
                    f += PF[(256 + ks*16 + bq*8 + ip)*PSF + lo*8 + bo];
                float gg = expf(-fmaxf(f + b_dg_x[ig], 0.f));
                float mm = Mc[ig*NB + b], xx = Xc[ig*NB + b];
                float xl = (mm > 0.f) ? xx : s->xlast[il*NB + b];
                s->xlast[il*NB + b] = xl;
                float xv = mm*xx + (1.f-mm)*(gg*xl + (1.f-gg)*x_mean[ig]);
                s->ximp[par][ig*NB + b] = xv;
                uint32_t la = s2u(&s->ximp[par][ig*NB + b]);
                #pragma unroll
                for (int r = 0; r < CSZ; r++)
                    if (r != rank) stc1(mapa_(la, (uint32_t)r), xv);
                s->xo4[(il*NB + b)*4 + u1] = xv;
                if (u1 == 3)
                    *(float4*)&out_x[((size_t)(b0+b)*DI + ig)*DT + (t+1) - 3] =
                        *(const float4*)&s->xo4[(il*NB + b)*4];
            }
            CLUSTER_SYNC();   // ximp(t+1) full everywhere
            xm_matmul(s, tid, rank, (const ulonglong2*)s->ximp[par],
                      (const ulonglong2*)&s->in4[(1*4+u1)*DI*NB]);
            __syncthreads();
            xm_combine(s, tid, PF);
        }
        __syncthreads();

        // ---- wait for all CTAs ----
        if (tid == 0) {
            while (*(volatile unsigned*)&d_bar[t] < (unsigned)NBLK) { __nanosleep(32); }
            __threadfence();
        }
        __syncthreads();

        // ---- Phase D: BN stats ----
        if (tid < DJ) {
            int jg = colbase + tid, buf = t & 1;
            const float4* ps = (const float4*)d_psum[buf][jg];
            const float4* pq = (const float4*)d_psq [buf][jg];
            float s1 = 0.f, s2 = 0.f;
            #pragma unroll
            for (int pp = 0; pp < NCLU/4; pp++) {
                float4 a4 = __ldcg(ps + pp);
                float4 c4 = __ldcg(pq + pp);
                s1 += (a4.x + a4.y) + (a4.z + a4.w);
                s2 += (c4.x + c4.y) + (c4.z + c4.w);
            }
            float mu  = s1 * (1.f/(float)DB);
            float var = fmaf(s2, 1.f/(float)DB, -mu*mu);
            float rs  = rsqrtf(var + 1e-5f);
            float aa  = rs * bn_g[jg];
            s->a[tid] = aa;
            s->c[tid] = fmaf(-mu, aa, bn_b[jg]);
        }
        __syncthreads();

        // ---- Phase E: normalize, carry h, coalesced out_h, hdec(t+1) ----
        if (tid < 256) {
            int bq4 = tid >> 6, j = tid & 63, jg = colbase + j;
            float aa = s->a[j], cc = s->c[j];
            float4 hd4; float* hp = (float*)&hd4;
            #pragma unroll
            for (int u2 = 0; u2 < 4; u2++) {
                int b = bq4*4 + u2;
                float hb = fmaf(s->hnew[j*HST + b], aa, cc);
                s->h[j*HST + b] = hb;
                out_h[((size_t)(b0+b)*DT + t)*DH + jg] = hb;
                hp[u2] = s->gbuf[j*NB + b] * hb;
            }
            *(float4*)&s->hdec[jg*NB + bq4*4] = hd4;
            uint32_t la = s2u(&s->hdec[jg*NB + bq4*4]);
            #pragma unroll
            for (int r = 0; r < CSZ; r++)
                if (r != rank) stc4(mapa_(la, (uint32_t)r), hd4);
        }
        __syncthreads();

        // ---- Phase F: distributed y-head (16 warps x 2 tasks) ----
        {
            int w = tid >> 5, lane = tid & 31;
            #pragma unroll
            for (int it = 0; it < 2; it++) {
                int task = w*2 + it;
                int b = task >> 1, o = task & 1;
                float acc = s->h[lane*HST + b]      * __ldg(&w_hy[o*DH + colbase + lane])
                          + s->h[(lane+32)*HST + b] * __ldg(&w_hy[o*DH + colbase + lane + 32]);
                #pragma unroll
                for (int off = 16; off; off >>= 1)
                    acc += __shfl_xor_sync(0xffffffffu, acc, off);
                if (lane == 0) {
                    if (rank == 0) s->ypart[0][task] = acc;
                    else stc1(mapa_(s2u(&s->ypart[rank][task]), 0u), acc);
                }
            }
        }
        CLUSTER_SYNC();   // ypart + hdec exchanges complete
        if (rank == 0 && tid < 32) {
            int b = tid >> 1, o = tid & 1;
            float v = s->ypart[0][tid] + s->ypart[1][tid]
                    + s->ypart[2][tid] + s->ypart[3][tid] + b_hy[o];
            out_y[((size_t)(b0+b)*DT + t)*DO + o] = 1.f / (1.f + expf(-v));
        }
        __syncthreads();
    }
}

extern "C" void kernel_launch(void* const* d_in, const int* in_sizes, int n_in,
                              void* d_out, int out_size) {
    cudaFuncSetAttribute(grud_kernel, cudaFuncAttributeMaxDynamicSharedMemorySize,
                         (int)sizeof(Smem));
    grud_kernel<<<NBLK, TPB, sizeof(Smem)>>>(
        (const float*)d_in[0],  (const float*)d_in[1],
        (const float*)d_in[2],  (const float*)d_in[3],
        (const float*)d_in[4],  (const float*)d_in[5],
        (const float*)d_in[6],  (const float*)d_in[7],
        (const float*)d_in[8],  (const float*)d_in[9],
        (const float*)d_in[10], (const float*)d_in[11],
        (const float*)d_in[12], (const float*)d_in[13],
        (const float*)d_in[14], (const float*)d_in[15],
        (const float*)d_in[16], (const float*)d_in[17],
        (const float*)d_in[18], (const float*)d_in[19],
        (const float*)d_in[20], (const float*)d_in[21],
        (float*)d_out);
}

// round 12
// speedup vs baseline: 1.0955x; 1.0456x over previous
#include <cuda_runtime.h>
#include <math.h>
#include <stdint.h>

typedef unsigned long long ull;

#define TPB  512
#define NBLK 128
#define CSZ  4
#define NCLU 32
#define DB 512
#define DI 64
#define DH 256
#define DJ 64     /* j cols per CTA */
#define NB 16     /* batches per cluster */
#define DO 2
#define DT 200
#define HST 17    /* padded stride for h / hnew */
#define PSTR 9    /* ull stride per partial slot (bank-conflict pad) */
#define PSF 18    /* float stride per slot */

// ---------------- static device scratch ----------------
__device__ float d_wdgxT[DI*DI];
__device__ float d_wdghT[DI*DH];
__device__ float d_wxzT[DI*DH], d_wmzT[DI*DH];
__device__ float d_wxrT[DI*DH], d_wmrT[DI*DH];
__device__ float d_wxhT[DI*DH], d_wmhT[DI*DH];
__device__ float d_whzT[DH*DH], d_whrT[DH*DH], d_whhT[DH*DH];
__device__ float d_psum[2][DH][NCLU];
__device__ float d_psq [2][DH][NCLU];
__device__ unsigned d_bar[DT];
__device__ unsigned g_count = 0;
__device__ volatile unsigned g_gen = 0;

// ---------------- shared layout (~143KB) ----------------
struct __align__(16) Smem {
    float in4[3*4*DI*NB];      // [c][u][i][b] staged 4 steps
    float ximp[2][DI*NB];      // double-buffered (parity), exchanged
    float xlast[16*NB];
    float xo4[16*NB*4];
    float hdec[DH*NB];         // full, exchanged
    float rh[DH*NB];           // full, exchanged
    float z[DJ*NB];            // z gate; reused as w_hy cache in epilogue
    float gbuf[DJ*NB];         // gamma_h(t+1)
    float h[DJ*HST];
    float hnew[DJ*HST];
    float a[DJ], c[DJ];
    ull   p[TPB*PSTR];         // padded partials
};

// ---------------- helpers ----------------
__device__ __forceinline__ ull pk(float w) {
    ull r; unsigned u = __float_as_uint(w);
    asm("mov.b64 %0, {%1, %1};" : "=l"(r) : "r"(u));
    return r;
}
__device__ __forceinline__ void dfma(ull& d, ull a, ull b) {
    asm("fma.rn.f32x2 %0, %1, %2, %0;" : "+l"(d) : "l"(a), "l"(b));
}
#define ADD2(d, a) asm("add.rn.f32x2 %0, %0, %1;" : "+l"(d) : "l"(a))
__device__ __forceinline__ float sigf(float x) { return 1.f / (1.f + expf(-x)); }

__device__ __forceinline__ uint32_t s2u(const void* p) {
    uint32_t a;
    asm("{ .reg .u64 t; cvta.to.shared.u64 t, %1; cvt.u32.u64 %0, t; }" : "=r"(a) : "l"(p));
    return a;
}
__device__ __forceinline__ uint32_t mapa_(uint32_t a, uint32_t r) {
    uint32_t o; asm("mapa.shared::cluster.u32 %0, %1, %2;" : "=r"(o) : "r"(a), "r"(r));
    return o;
}
__device__ __forceinline__ void stc1(uint32_t a, float v) {
    asm volatile("st.shared::cluster.b32 [%0], %1;" :: "r"(a), "r"(__float_as_uint(v)) : "memory");
}
__device__ __forceinline__ void stc4(uint32_t a, float4 v) {
    asm volatile("st.shared::cluster.v4.b32 [%0], {%1,%2,%3,%4};" :: "r"(a),
        "r"(__float_as_uint(v.x)), "r"(__float_as_uint(v.y)),
        "r"(__float_as_uint(v.z)), "r"(__float_as_uint(v.w)) : "memory");
}
#define CLUSTER_SYNC() do { \
    asm volatile("barrier.cluster.arrive.aligned;" ::: "memory"); \
    asm volatile("barrier.cluster.wait.aligned;"   ::: "memory"); \
} while (0)

// streamed weights [k][cols] float2 stride WS; state v = [k][16b]
template<int WS>
__device__ __forceinline__ void accG(const float2* __restrict__ w, int wcol,
                                     const ulonglong2* __restrict__ v, int bq,
                                     int k0, int k1, ull* A) {
    #pragma unroll 8
    for (int k = k0; k < k1; k++) {
        float2 ww = __ldg(&w[(size_t)k*WS + wcol]);
        ulonglong2 v0 = v[k*4 + bq*2], v1 = v[k*4 + bq*2 + 1];
        ull w0 = pk(ww.x), w1 = pk(ww.y);
        dfma(A[0], w0, v0.x); dfma(A[1], w0, v0.y);
        dfma(A[2], w0, v1.x); dfma(A[3], w0, v1.y);
        dfma(A[4], w1, v0.x); dfma(A[5], w1, v0.y);
        dfma(A[6], w1, v1.x); dfma(A[7], w1, v1.y);
    }
}

__device__ __forceinline__ void stP(Smem* s, int slot, const ull* A) {
    ull* dst = &s->p[(size_t)slot*PSTR];
    #pragma unroll
    for (int q = 0; q < 8; q++) dst[q] = A[q];
}

__device__ __forceinline__ void tpose(const float* __restrict__ src,
                                      float* __restrict__ dst,
                                      int J, int K, int g0, int gs) {
    int n = J * K;
    for (int e = g0; e < n; e += gs) {
        int k = e / J, j = e - k * J;
        dst[e] = src[j * K + k];
    }
}

__device__ __forceinline__ void grid_barrier() {
    __syncthreads();
    if (threadIdx.x == 0) {
        __threadfence();
        unsigned gen = g_gen;
        if (atomicAdd(&g_count, 1u) == (unsigned)(gridDim.x - 1)) {
            g_count = 0u;
            __threadfence();
            g_gen = gen + 1u;
        } else {
            while (g_gen == gen) { __nanosleep(64); }
        }
        __threadfence();
    }
    __syncthreads();
}

__global__ void __cluster_dims__(CSZ,1,1) __launch_bounds__(TPB,1) grud_kernel(
    const float* __restrict__ in,     const float* __restrict__ x_mean,
    const float* __restrict__ w_dg_x, const float* __restrict__ b_dg_x,
    const float* __restrict__ w_dg_h, const float* __restrict__ b_dg_h,
    const float* __restrict__ w_xz,   const float* __restrict__ w_hz,
    const float* __restrict__ w_mz,   const float* __restrict__ b_z,
    const float* __restrict__ w_xr,   const float* __restrict__ w_hr,
    const float* __restrict__ w_mr,   const float* __restrict__ b_r,
    const float* __restrict__ w_xh,   const float* __restrict__ w_hh,
    const float* __restrict__ w_mh,   const float* __restrict__ b_h,
    const float* __restrict__ w_hy,   const float* __restrict__ b_hy,
    const float* __restrict__ bn_g,   const float* __restrict__ bn_b,
    float* __restrict__ out)
{
    extern __shared__ __align__(16) char raw[];
    Smem* s = (Smem*)raw;

    const int tid  = threadIdx.x;
    const int blk  = blockIdx.x;
    const int clu  = blk >> 2;
    const int rank = blk & 3;
    const int b0   = clu * NB;
    const int colbase = rank * DJ;

    float* __restrict__ out_y = out;
    float* __restrict__ out_h = out   + (size_t)DB * DT * DO;
    float* __restrict__ out_x = out_h + (size_t)DB * DT * DH;
    float* __restrict__ out_m = out_x + (size_t)DB * DI * DT;

    // -------- init: transposes, counters, mask copy --------
    {
        int g0 = blk * TPB + tid, gs = NBLK * TPB;
        tpose(w_dg_x, d_wdgxT, DI, DI, g0, gs);
        tpose(w_dg_h, d_wdghT, DH, DI, g0, gs);
        tpose(w_xz,   d_wxzT,  DH, DI, g0, gs);
        tpose(w_mz,   d_wmzT,  DH, DI, g0, gs);
        tpose(w_xr,   d_wxrT,  DH, DI, g0, gs);
        tpose(w_mr,   d_wmrT,  DH, DI, g0, gs);
        tpose(w_xh,   d_wxhT,  DH, DI, g0, gs);
        tpose(w_mh,   d_wmhT,  DH, DI, g0, gs);
        tpose(w_hz,   d_whzT,  DH, DH, g0, gs);
        tpose(w_hr,   d_whrT,  DH, DH, g0, gs);
        tpose(w_hh,   d_whhT,  DH, DH, g0, gs);
        if (blk == 0 && tid < DT) d_bar[tid] = 0u;
        for (int lb = 0; lb < 4; lb++) {
            int b = b0 + rank*4 + lb;
            const float4* src = (const float4*)(in + ((size_t)b*3 + 1) * DI * DT);
            float4* dst = (float4*)(out_m + (size_t)b * DI * DT);
            for (int e = tid; e < DI*DT/4; e += TPB) dst[e] = src[e];
        }
    }
    for (int e = tid; e < DJ*HST; e += TPB) s->h[e] = 0.f;
    for (int e = tid; e < DH*NB; e += TPB) s->hdec[e] = 0.f;
    if (tid < 16*NB) s->xlast[tid] = 0.f;

    grid_barrier();   // weights + counters visible

    const float* PF = (const float*)s->p;

    // -------- prologue: stage steps 0..3, Phase A for t=0 --------
    {
        for (int e = tid; e < 3*DI*NB; e += TPB) {
            int cc = e >> 10, r = e & 1023;
            int i = r >> 4, b = r & 15;
            float4 v = *(const float4*)&in[(((size_t)(b0+b)*3 + cc)*DI + i)*DT + 0];
            s->in4[((cc*4+0)*DI + i)*NB + b] = v.x;
            s->in4[((cc*4+1)*DI + i)*NB + b] = v.y;
            s->in4[((cc*4+2)*DI + i)*NB + b] = v.z;
            s->in4[((cc*4+3)*DI + i)*NB + b] = v.w;
        }
        __syncthreads();
        const ulonglong2* DD = (const ulonglong2*)&s->in4[(2*4+0)*DI*NB];
        if (tid < 256) {
            int jp = tid & 31, bq = (tid>>5)&1, ks = tid>>6;
            ull A[8] = {0,0,0,0,0,0,0,0};
            accG<128>((const float2*)d_wdghT, rank*32 + jp, DD, bq, ks*16, ks*16+16, A);
            stP(s, tid, A);
        } else if (tid < 384) {
            int idx = tid - 256;
            int ip = idx & 7, bq = (idx>>3)&1, ks = idx>>4;
            ull A[8] = {0,0,0,0,0,0,0,0};
            accG<32>((const float2*)d_wdgxT, rank*8 + ip, DD, bq, ks*8, ks*8+8, A);
            stP(s, tid, A);
        }
        __syncthreads();
        const float* Xc = &s->in4[(0*4+0)*DI*NB];
        const float* Mc = &s->in4[(1*4+0)*DI*NB];
        #pragma unroll
        for (int hf = 0; hf < 2; hf++) {
            int idx = hf*TPB + tid;
            int b = idx & 15, j = idx >> 4;
            int jp = j >> 1, lo = j & 1, bq = b >> 3, bo = b & 7;
            float f = 0.f;
            #pragma unroll
            for (int ks = 0; ks < 4; ks++) f += PF[(ks*64 + bq*32 + jp)*PSF + lo*8 + bo];
            s->gbuf[j*NB + b] = expf(-fmaxf(f + b_dg_h[colbase + j], 0.f));
        }
        if (tid < 256) {
            int il = tid >> 4, b = tid & 15;
            int ip = il >> 1, lo = il & 1, bq = b >> 3, bo = b & 7;
            int ig = rank*16 + il;
            float f = 0.f;
            #pragma unroll
            for (int ks = 0; ks < 8; ks++) f += PF[(256 + ks*16 + bq*8 + ip)*PSF + lo*8 + bo];
            float gg = expf(-fmaxf(f + b_dg_x[ig], 0.f));
            float mm = Mc[ig*NB + b], xx = Xc[ig*NB + b];
            float xl = (mm > 0.f) ? xx : s->xlast[il*NB + b];
            s->xlast[il*NB + b] = xl;
            float xv = mm*xx + (1.f-mm)*(gg*xl + (1.f-gg)*x_mean[ig]);
            s->ximp[0][ig*NB + b] = xv;
            uint32_t la = s2u(&s->ximp[0][ig*NB + b]);
            #pragma unroll
            for (int r = 0; r < CSZ; r++)
                if (r != rank) stc1(mapa_(la, (uint32_t)r), xv);
            s->xo4[(il*NB + b)*4 + 0] = xv;
        }
        CLUSTER_SYNC();
    }

    for (int t = 0; t < DT; t++) {
        const int u = t & 3;
        const ulonglong2* XI = (const ulonglong2*)s->ximp[t & 1];
        const ulonglong2* HD = (const ulonglong2*)s->hdec;
        const ulonglong2* RH = (const ulonglong2*)s->rh;
        const ulonglong2* MM = (const ulonglong2*)&s->in4[(1*4+u)*DI*NB];

        // ---- Phase B matmul: z (0..255) / r (256..511) ----
        {
            int g = tid >> 8, ks = (tid>>6)&3, bq = (tid>>5)&1, jp = tid & 31;
            const float2* wx = (const float2*)(g ? d_wxrT : d_wxzT);
            const float2* wm = (const float2*)(g ? d_wmrT : d_wmzT);
            const float2* wh = (const float2*)(g ? d_whrT : d_whzT);
            int wc = rank*32 + jp;
            ull A[8] = {0,0,0,0,0,0,0,0};
            switch (ks) {
                case 0: accG<128>(wx, wc, XI, bq, 0, 64, A);
                        accG<128>(wm, wc, MM, bq, 0, 32, A); break;
                case 1: accG<128>(wm, wc, MM, bq, 32, 64, A);
                        accG<128>(wh, wc, HD, bq, 0, 64, A); break;
                case 2: accG<128>(wh, wc, HD, bq, 64, 160, A); break;
                default: accG<128>(wh, wc, HD, bq, 160, 256, A); break;
            }
            stP(s, tid, A);
        }
        __syncthreads();

        // ---- Phase B combine (ull/f32x2): z local; rh + exchange ----
        if (tid < 256) {
            int g = tid >> 7, idx = tid & 127;
            int j = idx >> 1, bq = idx & 1;
            int jp = j >> 1, lo = j & 1, jg = colbase + j;
            const ull* P = s->p;
            int base = (g*256 + bq*32 + jp)*PSTR + lo*4;
            ull U0 = P[base], U1 = P[base+1], U2 = P[base+2], U3 = P[base+3];
            #pragma unroll
            for (int ks = 1; ks < 4; ks++) {
                int o2 = base + ks*64*PSTR;
                ADD2(U0, P[o2]); ADD2(U1, P[o2+1]);
                ADD2(U2, P[o2+2]); ADD2(U3, P[o2+3]);
            }
            float f[8];
            ((ull*)f)[0]=U0; ((ull*)f)[1]=U1; ((ull*)f)[2]=U2; ((ull*)f)[3]=U3;
            if (g == 0) {
                float bzv = b_z[jg];
                float4 z0, z1; float* zp0 = (float*)&z0; float* zp1 = (float*)&z1;
                #pragma unroll
                for (int q = 0; q < 4; q++) {
                    zp0[q] = sigf(f[q] + bzv);
                    zp1[q] = sigf(f[4+q] + bzv);
                }
                *(float4*)&s->z[j*NB + bq*8]     = z0;
                *(float4*)&s->z[j*NB + bq*8 + 4] = z1;
            } else {
                float brv = b_r[jg];
                float4 r0, r1; float* rp0 = (float*)&r0; float* rp1 = (float*)&r1;
                #pragma unroll
                for (int q = 0; q < 4; q++) {
                    rp0[q] = sigf(f[q] + brv)   * s->hdec[jg*NB + bq*8 + q];
                    rp1[q] = sigf(f[4+q] + brv) * s->hdec[jg*NB + bq*8 + 4 + q];
                }
                *(float4*)&s->rh[jg*NB + bq*8]     = r0;
                *(float4*)&s->rh[jg*NB + bq*8 + 4] = r1;
                uint32_t la = s2u(&s->rh[jg*NB + bq*8]);
                #pragma unroll
                for (int r = 0; r < CSZ; r++)
                    if (r != rank) {
                        uint32_t ra = mapa_(la, (uint32_t)r);
                        stc4(ra, r0); stc4(ra + 16, r1);
                    }
            }
        }
        CLUSTER_SYNC();   // rh full everywhere

        // ---- Phase C matmul: h_tilde preact, 8 k-splits of 48 ----
        {
            int ks = tid >> 6, bq = (tid>>5)&1, jp = tid & 31;
            const float2* wxh2 = (const float2*)d_wxhT;
            const float2* wmh2 = (const float2*)d_wmhT;
            const float2* whh2 = (const float2*)d_whhT;
            int wc = rank*32 + jp;
            ull A[8] = {0,0,0,0,0,0,0,0};
            switch (ks) {
                case 0: accG<128>(wxh2, wc, XI, bq, 0, 48, A); break;
                case 1: accG<128>(wxh2, wc, XI, bq, 48, 64, A);
                        accG<128>(wmh2, wc, MM, bq, 0, 32, A); break;
                case 2: accG<128>(wmh2, wc, MM, bq, 32, 64, A);
                        accG<128>(whh2, wc, RH, bq, 0, 16, A); break;
                case 3: accG<128>(whh2, wc, RH, bq, 16, 64, A); break;
                case 4: accG<128>(whh2, wc, RH, bq, 64, 112, A); break;
                case 5: accG<128>(whh2, wc, RH, bq, 112, 160, A); break;
                case 6: accG<128>(whh2, wc, RH, bq, 160, 208, A); break;
                default: accG<128>(whh2, wc, RH, bq, 208, 256, A); break;
            }
            stP(s, tid, A);
        }
        __syncthreads();

        // ---- Phase C combine (ull/f32x2, tid<128) + restage in4 ----
        if (tid < 128) {
            int j = tid >> 1, bq = tid & 1;
            int jp = j >> 1, lo = j & 1, jg = colbase + j;
            const ull* P = s->p;
            int base = (bq*32 + jp)*PSTR + lo*4;
            ull U0 = P[base], U1 = P[base+1], U2 = P[base+2], U3 = P[base+3];
            #pragma unroll
            for (int ks = 1; ks < 8; ks++) {
                int o2 = base + ks*64*PSTR;
                ADD2(U0, P[o2]); ADD2(U1, P[o2+1]);
                ADD2(U2, P[o2+2]); ADD2(U3, P[o2+3]);
            }
            float f[8];
            ((ull*)f)[0]=U0; ((ull*)f)[1]=U1; ((ull*)f)[2]=U2; ((ull*)f)[3]=U3;
            float bh = b_h[jg];
            float ps = 0.f, pq = 0.f;
            #pragma unroll
            for (int q = 0; q < 8; q++) {
                int b = bq*8 + q;
                float ht = tanhf(f[q] + bh);
                float zz = s->z[j*NB + b], hd = s->hdec[jg*NB + b];
                float h1 = (1.f - zz)*hd + zz*ht;
                s->hnew[j*HST + b] = h1;
                ps += h1; pq += h1*h1;
            }
            ps += __shfl_xor_sync(0xffffffffu, ps, 1);
            pq += __shfl_xor_sync(0xffffffffu, pq, 1);
            if (bq == 0) {
                int buf = t & 1;
                d_psum[buf][jg][clu] = ps;
                d_psq [buf][jg][clu] = pq;
            }
        }
        if ((t+1) < DT && (((t+1) & 3) == 0)) {
            for (int e = tid; e < 3*DI*NB; e += TPB) {
                int cc = e >> 10, r = e & 1023;
                int i = r >> 4, b = r & 15;
                float4 v = *(const float4*)&in[(((size_t)(b0+b)*3 + cc)*DI + i)*DT + (t+1)];
                s->in4[((cc*4+0)*DI + i)*NB + b] = v.x;
                s->in4[((cc*4+1)*DI + i)*NB + b] = v.y;
                s->in4[((cc*4+2)*DI + i)*NB + b] = v.z;
                s->in4[((cc*4+3)*DI + i)*NB + b] = v.w;
            }
        }
        __syncthreads();

        // ---- arrive at grid barrier, then Phase A(t+1) in its shadow ----
        if (tid == 0) { __threadfence(); atomicAdd(&d_bar[t], 1u); }

        if ((t+1) < DT) {
            const int u1 = (t+1) & 3;
            const ulonglong2* DD = (const ulonglong2*)&s->in4[(2*4+u1)*DI*NB];
            if (tid < 256) {
                int jp = tid & 31, bq = (tid>>5)&1, ks = tid>>6;
                ull A[8] = {0,0,0,0,0,0,0,0};
                accG<128>((const float2*)d_wdghT, rank*32 + jp, DD, bq, ks*16, ks*16+16, A);
                stP(s, tid, A);
            } else if (tid < 384) {
                int idx = tid - 256;
                int ip = idx & 7, bq = (idx>>3)&1, ks = idx>>4;
                ull A[8] = {0,0,0,0,0,0,0,0};
                accG<32>((const float2*)d_wdgxT, rank*8 + ip, DD, bq, ks*8, ks*8+8, A);
                stP(s, tid, A);
            }
        }
        __syncthreads();
        if ((t+1) < DT) {
            const int u1 = (t+1) & 3;
            const int par = (t+1) & 1;
            const float* Xc = &s->in4[(0*4+u1)*DI*NB];
            const float* Mc = &s->in4[(1*4+u1)*DI*NB];
            #pragma unroll
            for (int hf = 0; hf < 2; hf++) {
                int idx = hf*TPB + tid;
                int b = idx & 15, j = idx >> 4;
                int jp = j >> 1, lo = j & 1, bq = b >> 3, bo = b & 7;
                float f = 0.f;
                #pragma unroll
                for (int ks = 0; ks < 4; ks++)
                    f += PF[(ks*64 + bq*32 + jp)*PSF + lo*8 + bo];
                s->gbuf[j*NB + b] = expf(-fmaxf(f + b_dg_h[colbase + j], 0.f));
            }
            if (tid < 256) {
                int il = tid >> 4, b = tid & 15;
                int ip = il >> 1, lo = il & 1, bq = b >> 3, bo = b & 7;
                int ig = rank*16 + il;
                float f = 0.f;
                #pragma unroll
                for (int ks = 0; ks < 8; ks++)
                    f += PF[(256 + ks*16 + bq*8 + ip)*PSF + lo*8 + bo];
                float gg = expf(-fmaxf(f + b_dg_x[ig], 0.f));
                float mm = Mc[ig*NB + b], xx = Xc[ig*NB + b];
                float xl = (mm > 0.f) ? xx : s->xlast[il*NB + b];
                s->xlast[il*NB + b] = xl;
                float xv = mm*xx + (1.f-mm)*(gg*xl + (1.f-gg)*x_mean[ig]);
                s->ximp[par][ig*NB + b] = xv;
                uint32_t la = s2u(&s->ximp[par][ig*NB + b]);
                #pragma unroll
                for (int r = 0; r < CSZ; r++)
                    if (r != rank) stc1(mapa_(la, (uint32_t)r), xv);
                s->xo4[(il*NB + b)*4 + u1] = xv;
                if (u1 == 3)
                    *(float4*)&out_x[((size_t)(b0+b)*DI + ig)*DT + (t+1) - 3] =
                        *(const float4*)&s->xo4[(il*NB + b)*4];
            }
        }
        __syncthreads();

        // ---- wait for all CTAs ----
        if (tid == 0) {
            while (*(volatile unsigned*)&d_bar[t] < (unsigned)NBLK) { __nanosleep(32); }
            __threadfence();
        }
        __syncthreads();

        // ---- Phase D: BN stats ----
        if (tid < DJ) {
            int jg = colbase + tid, buf = t & 1;
            const float4* ps = (const float4*)d_psum[buf][jg];
            const float4* pq = (const float4*)d_psq [buf][jg];
            float s1 = 0.f, s2 = 0.f;
            #pragma unroll
            for (int pp = 0; pp < NCLU/4; pp++) {
                float4 a4 = __ldcg(ps + pp);
                float4 c4 = __ldcg(pq + pp);
                s1 += (a4.x + a4.y) + (a4.z + a4.w);
                s2 += (c4.x + c4.y) + (c4.z + c4.w);
            }
            float mu  = s1 * (1.f/(float)DB);
            float var = fmaf(s2, 1.f/(float)DB, -mu*mu);
            float rs  = rsqrtf(var + 1e-5f);
            float aa  = rs * bn_g[jg];
            s->a[tid] = aa;
            s->c[tid] = fmaf(-mu, aa, bn_b[jg]);
        }
        __syncthreads();

        // ---- Phase E: normalize, carry h, coalesced out_h, hdec(t+1) ----
        if (tid < 256) {
            int bq4 = tid >> 6, j = tid & 63, jg = colbase + j;
            float aa = s->a[j], cc = s->c[j];
            float4 hd4; float* hp = (float*)&hd4;
            #pragma unroll
            for (int u2 = 0; u2 < 4; u2++) {
                int b = bq4*4 + u2;
                float hb = fmaf(s->hnew[j*HST + b], aa, cc);
                s->h[j*HST + b] = hb;
                out_h[((size_t)(b0+b)*DT + t)*DH + jg] = hb;
                hp[u2] = s->gbuf[j*NB + b] * hb;
            }
            *(float4*)&s->hdec[jg*NB + bq4*4] = hd4;
            uint32_t la = s2u(&s->hdec[jg*NB + bq4*4]);
            #pragma unroll
            for (int r = 0; r < CSZ; r++)
                if (r != rank) stc4(mapa_(la, (uint32_t)r), hd4);
        }
        CLUSTER_SYNC();   // hdec + ximp exchanges complete (full block barrier)
    }

    // -------- epilogue: y = sigmoid(h @ w_hy^T + b) from out_h --------
    __threadfence();
    CLUSTER_SYNC();          // peers' out_h STG visible
    {
        float* swhy = s->z;  // 512-float cache
        if (tid < DO*DH) swhy[tid] = w_hy[tid];
        __syncthreads();
        float bhy0 = b_hy[0], bhy1 = b_hy[1];
        int w = tid >> 5, lane = tid & 31;
        for (int task = w; task < 4*DT*DO; task += 16) {
            int t = task >> 3, sub = task & 7;
            int lb = sub >> 1, o = sub & 1;
            int b = b0 + rank*4 + lb;
            const float* hrow = out_h + ((size_t)b*DT + t)*DH;
            float acc = 0.f;
            #pragma unroll
            for (int kk = 0; kk < 8; kk++)
                acc = fmaf(__ldcg(&hrow[lane + kk*32]), swhy[o*DH + lane + kk*32], acc);
            #pragma unroll
            for (int off = 16; off; off >>= 1)
                acc += __shfl_xor_sync(0xffffffffu, acc, off);
            if (lane == 0)
                out_y[((size_t)b*DT + t)*DO + o] =
                    1.f / (1.f + expf(-(acc + (o ? bhy1 : bhy0))));
        }
    }
}

extern "C" void kernel_launch(void* const* d_in, const int* in_sizes, int n_in,
                              void* d_out, int out_size) {
    cudaFuncSetAttribute(grud_kernel, cudaFuncAttributeMaxDynamicSharedMemorySize,
                         (int)sizeof(Smem));
    grud_kernel<<<NBLK, TPB, sizeof(Smem)>>>(
        (const float*)d_in[0],  (const float*)d_in[1],
        (const float*)d_in[2],  (const float*)d_in[3],
        (const float*)d_in[4],  (const float*)d_in[5],
        (const float*)d_in[6],  (const float*)d_in[7],
        (const float*)d_in[8],  (const float*)d_in[9],
        (const float*)d_in[10], (const float*)d_in[11],
        (const float*)d_in[12], (const float*)d_in[13],
        (const float*)d_in[14], (const float*)d_in[15],
        (const float*)d_in[16], (const float*)d_in[17],
        (const float*)d_in[18], (const float*)d_in[19],
        (const float*)d_in[20], (const float*)d_in[21],
        (float*)d_out);
}